// round 4
// baseline (speedup 1.0000x reference)
#include <cuda_runtime.h>

#define T_STEPS 512
#define Hdim    512
#define Bsz     256
#define INdim   8
#define NB      128   // CTAs, 1 per SM => co-resident => grid barrier safe
#define NT      512   // threads per CTA (16 warps for latency hiding)

// SMEM layout (float offsets)
#define WH0_OFF 0          // [512][32]  W_hh layer0 slice, k-major, rows interleaved
#define WI1_OFF 16384      // [512][32]  W_ih layer1 slice
#define WH1_OFF 32768      // [512][32]  W_hh layer1 slice
#define WI0_OFF 49152      // [8][32]    W_ih layer0 slice
#define B0_OFF  49408      // [32] combined bias layer0
#define B1_OFF  49440      // [32] combined bias layer1
#define SMEM_FLOATS 49472
#define SMEM_BYTES  (SMEM_FLOATS * 4)   // 197888 B < 227KB opt-in

// ---------------- global scratch (device statics: allocation-free) --------
__device__ float g_h0[2][Hdim][Bsz];   // layer0 h, double buffered, [col][batch]
__device__ float g_h1[2][Hdim][Bsz];   // layer1 h
__device__ float g_fch[256][Bsz];      // fc0 activations [row][batch]
__device__ unsigned g_arrive = 0;      // barrier arrive counter
__device__ unsigned g_gen    = 0;      // barrier release generation

// ---------------- f32x2 packed helpers ------------------------------------
__device__ __forceinline__ unsigned long long pack2(float x) {
    unsigned long long r;
    asm("mov.b64 %0, {%1,%2};" : "=l"(r)
        : "r"(__float_as_uint(x)), "r"(__float_as_uint(x)));
    return r;
}
__device__ __forceinline__ float2 unpack2(unsigned long long v) {
    unsigned lo, hi;
    asm("mov.b64 {%0,%1}, %2;" : "=r"(lo), "=r"(hi) : "l"(v));
    return make_float2(__uint_as_float(lo), __uint_as_float(hi));
}
__device__ __forceinline__ void fma2(unsigned long long& a,
                                     unsigned long long w,
                                     unsigned long long h) {
    asm("fma.rn.f32x2 %0, %1, %2, %0;" : "+l"(a) : "l"(w), "l"(h));
}
__device__ __forceinline__ float sigx(float x) { return 1.0f / (1.0f + __expf(-x)); }

// ---------------- software grid barrier (generation counter) --------------
__device__ __forceinline__ void grid_barrier() {
    __syncthreads();
    if (threadIdx.x == 0) {
        __threadfence();
        volatile unsigned* genp = &g_gen;
        unsigned snap = *genp;
        unsigned old = atomicAdd(&g_arrive, 1u);
        if (old == (unsigned)(NB - 1)) {
            g_arrive = 0u;       // safe: all other blocks are spinning on g_gen
            __threadfence();
            atomicAdd(&g_gen, 1u);
        } else {
            while (*genp == snap) { }
        }
        __threadfence();
    }
    __syncthreads();
}

// ---------------- one pipelined tick ---------------------------------------
// Tick t: layer0 step t (DOL0; recurrent term DWH0) and layer1 step t-1
// (DOL1; recurrent term DWH1). Each thread: 8 gate rows (4 f32x2) x 1 batch.
template<bool DOL0, bool DWH0, bool DOL1, bool DWH1>
__device__ __forceinline__ void tick(
    int t, int b, int rbase, int j0,
    const float* __restrict__ Wh0s, const float* __restrict__ Wi1s,
    const float* __restrict__ Wh1s, const float* __restrict__ Wi0s,
    const float* __restrict__ B0s,  const float* __restrict__ B1s,
    const float* __restrict__ u,
    float* c0, float* c1)
{
    const int pr  = (t - 1) & 1;   // parity of h0_{t-1}
    const int p1r = t & 1;         // parity of h1_{t-2}
    const int pw0 = t & 1;         // write parity for h0_t
    const int pw1 = (t - 1) & 1;   // write parity for h1_{t-1}

    unsigned long long a0[4], a1[4];

    if (DOL0) {
        const ulonglong2* bp = (const ulonglong2*)(B0s + rbase);
        ulonglong2 q0 = bp[0], q1 = bp[1];
        a0[0] = q0.x; a0[1] = q0.y; a0[2] = q1.x; a0[3] = q1.y;
        // input projection (IN = 8)
        const float4* xp = (const float4*)(u + ((size_t)b * T_STEPS + t) * INdim);
        float4 xa = xp[0], xb = xp[1];
        float xs[8] = {xa.x, xa.y, xa.z, xa.w, xb.x, xb.y, xb.z, xb.w};
        #pragma unroll
        for (int kk = 0; kk < INdim; ++kk) {
            const ulonglong2* wv = (const ulonglong2*)(Wi0s + kk * 32 + rbase);
            ulonglong2 w0 = wv[0], w1 = wv[1];
            unsigned long long hx = pack2(xs[kk]);
            fma2(a0[0], w0.x, hx); fma2(a0[1], w0.y, hx);
            fma2(a0[2], w1.x, hx); fma2(a0[3], w1.y, hx);
        }
    }
    if (DOL1) {
        const ulonglong2* bp = (const ulonglong2*)(B1s + rbase);
        ulonglong2 q0 = bp[0], q1 = bp[1];
        a1[0] = q0.x; a1[1] = q0.y; a1[2] = q1.x; a1[3] = q1.y;
    }

    if (DWH0 || DOL1) {
        const float* __restrict__ h0p = &g_h0[pr][0][0];
        const float* __restrict__ h1p = &g_h1[p1r][0][0];
        #pragma unroll 8
        for (int k = 0; k < Hdim; ++k) {
            float v = __ldcg(h0p + k * Bsz + b);
            unsigned long long hh = pack2(v);
            if (DWH0) {
                const ulonglong2* wv = (const ulonglong2*)(Wh0s + k * 32 + rbase);
                ulonglong2 w0 = wv[0], w1 = wv[1];
                fma2(a0[0], w0.x, hh); fma2(a0[1], w0.y, hh);
                fma2(a0[2], w1.x, hh); fma2(a0[3], w1.y, hh);
            }
            if (DOL1) {
                const ulonglong2* wv = (const ulonglong2*)(Wi1s + k * 32 + rbase);
                ulonglong2 w0 = wv[0], w1 = wv[1];
                fma2(a1[0], w0.x, hh); fma2(a1[1], w0.y, hh);
                fma2(a1[2], w1.x, hh); fma2(a1[3], w1.y, hh);
                if (DWH1) {
                    float g = __ldcg(h1p + k * Bsz + b);
                    unsigned long long gg = pack2(g);
                    const ulonglong2* uv = (const ulonglong2*)(Wh1s + k * 32 + rbase);
                    ulonglong2 u0 = uv[0], u1 = uv[1];
                    fma2(a1[0], u0.x, gg); fma2(a1[1], u0.y, gg);
                    fma2(a1[2], u1.x, gg); fma2(a1[3], u1.y, gg);
                }
            }
        }
    }

    // activations + cell update + h writes
    if (DOL0) {
        #pragma unroll
        for (int cc = 0; cc < 2; ++cc) {
            float2 ifp = unpack2(a0[cc * 2 + 0]);
            float2 gop = unpack2(a0[cc * 2 + 1]);
            float ig = sigx(ifp.x), fg = sigx(ifp.y);
            float gg = tanhf(gop.x), og = sigx(gop.y);
            float c = fg * c0[cc] + ig * gg;
            c0[cc] = c;
            float h = og * tanhf(c);
            int j = j0 + (rbase >> 2) + cc;
            __stcg(&g_h0[pw0][j][b], h);
        }
    }
    if (DOL1) {
        #pragma unroll
        for (int cc = 0; cc < 2; ++cc) {
            float2 ifp = unpack2(a1[cc * 2 + 0]);
            float2 gop = unpack2(a1[cc * 2 + 1]);
            float ig = sigx(ifp.x), fg = sigx(ifp.y);
            float gg = tanhf(gop.x), og = sigx(gop.y);
            float c = fg * c1[cc] + ig * gg;
            c1[cc] = c;
            float h = og * tanhf(c);
            int j = j0 + (rbase >> 2) + cc;
            __stcg(&g_h1[pw1][j][b], h);
        }
    }
}

// ---------------------------------------------------------------------------
__global__ void __launch_bounds__(NT, 1)
lstm_persistent(const float* __restrict__ u,
                const float* __restrict__ wih0, const float* __restrict__ whh0,
                const float* __restrict__ bih0, const float* __restrict__ bhh0,
                const float* __restrict__ wih1, const float* __restrict__ whh1,
                const float* __restrict__ bih1, const float* __restrict__ bhh1,
                const float* __restrict__ fcw0, const float* __restrict__ fcb0,
                const float* __restrict__ fcw1, const float* __restrict__ fcb1,
                float* __restrict__ out)
{
    extern __shared__ float smem[];
    float* Wh0s = smem + WH0_OFF;
    float* Wi1s = smem + WI1_OFF;
    float* Wh1s = smem + WH1_OFF;
    float* Wi0s = smem + WI0_OFF;
    float* B0s  = smem + B0_OFF;
    float* B1s  = smem + B1_OFF;

    const int tid = threadIdx.x;
    const int cg  = blockIdx.x >> 1;     // column group 0..63
    const int bg  = blockIdx.x & 1;      // batch half
    const int j0  = cg * 8;              // first hidden column of slice
    const int rq  = tid >> 7;            // row quarter 0..3 (8 gate rows each)
    const int bq  = tid & 127;           // batch lane 0..127
    const int rbase = rq * 8;
    const int b = bg * 128 + bq;         // this thread's batch element

    // ---- one-time weight staging into SMEM ----
    // local gate row r = jj*4 + g  (jj = col within slice, g = i,f,g,o)
    for (int i = tid; i < 32 * Hdim; i += NT) {
        int r = i & 31, k = i >> 5;
        int jj = r >> 2, g = r & 3;
        int grow = g * Hdim + j0 + jj;
        Wh0s[i] = whh0[grow * Hdim + k];
        Wi1s[i] = wih1[grow * Hdim + k];
        Wh1s[i] = whh1[grow * Hdim + k];
    }
    if (tid < 256) {
        int r = tid & 31, k = tid >> 5;  // covers [8][32] exactly
        int jj = r >> 2, g = r & 3;
        int grow = g * Hdim + j0 + jj;
        Wi0s[k * 32 + r] = wih0[grow * INdim + k];
    }
    if (tid < 32) {
        int jj = tid >> 2, g = tid & 3;
        int grow = g * Hdim + j0 + jj;
        B0s[tid] = bih0[grow] + bhh0[grow];
        B1s[tid] = bih1[grow] + bhh1[grow];
    }
    __syncthreads();

    float c0[2] = {0.f, 0.f};
    float c1[2] = {0.f, 0.f};

    // ---- pipelined time loop ----
    tick<true, false, false, false>(0, b, rbase, j0, Wh0s, Wi1s, Wh1s, Wi0s, B0s, B1s, u, c0, c1);
    grid_barrier();
    tick<true, true, true, false>(1, b, rbase, j0, Wh0s, Wi1s, Wh1s, Wi0s, B0s, B1s, u, c0, c1);
    grid_barrier();
    for (int t = 2; t < T_STEPS; ++t) {
        tick<true, true, true, true>(t, b, rbase, j0, Wh0s, Wi1s, Wh1s, Wi0s, B0s, B1s, u, c0, c1);
        grid_barrier();
    }
    tick<false, false, true, true>(T_STEPS, b, rbase, j0, Wh0s, Wi1s, Wh1s, Wi0s, B0s, B1s, u, c0, c1);
    grid_barrier();

    // ---- FC head stage A: fch[r][b] = tanh(fcw0[r,:] . h1_T[:,b] + fcb0[r]) ----
    {
        int gid = blockIdx.x * NT + tid;   // 0..65535 = 256 rows x 256 batches
        int r  = gid >> 8;
        int bb = gid & 255;
        const float* __restrict__ wrow  = fcw0 + (size_t)r * Hdim;
        const float* __restrict__ hbase = &g_h1[1][0][0];   // h1_{511} parity
        float acc = 0.f;
        #pragma unroll 8
        for (int k = 0; k < Hdim; ++k) {
            acc += __ldg(wrow + k) * __ldcg(hbase + k * Bsz + bb);
        }
        __stcg(&g_fch[r][bb], tanhf(acc + __ldg(fcb0 + r)));
    }
    grid_barrier();

    // ---- stage B (block 0): final 2-wide FC + affine ----
    if (blockIdx.x == 0 && tid < 256) {
        int bb = tid;
        float s0 = __ldg(fcb1 + 0), s1 = __ldg(fcb1 + 1);
        #pragma unroll 8
        for (int k = 0; k < 256; ++k) {
            float v = __ldcg(&g_fch[k][bb]);
            s0 += v * __ldg(fcw1 + k);
            s1 += v * __ldg(fcw1 + 256 + k);
        }
        const float scale = 0.5f * (4.2f - 2.5f);
        out[bb * 2 + 0] = (s0 + 1.0f) * scale + 2.5f;
        out[bb * 2 + 1] = (s1 + 1.0f) * scale + 2.5f;
    }
}

// ---------------------------------------------------------------------------
extern "C" void kernel_launch(void* const* d_in, const int* in_sizes, int n_in,
                              void* d_out, int out_size) {
    (void)in_sizes; (void)n_in; (void)out_size;
    const float* u    = (const float*)d_in[0];
    const float* wih0 = (const float*)d_in[1];
    const float* whh0 = (const float*)d_in[2];
    const float* bih0 = (const float*)d_in[3];
    const float* bhh0 = (const float*)d_in[4];
    const float* wih1 = (const float*)d_in[5];
    const float* whh1 = (const float*)d_in[6];
    const float* bih1 = (const float*)d_in[7];
    const float* bhh1 = (const float*)d_in[8];
    const float* fcw0 = (const float*)d_in[9];
    const float* fcb0 = (const float*)d_in[10];
    const float* fcw1 = (const float*)d_in[11];
    const float* fcb1 = (const float*)d_in[12];
    float* out = (float*)d_out;

    cudaFuncSetAttribute(lstm_persistent,
                         cudaFuncAttributeMaxDynamicSharedMemorySize, SMEM_BYTES);
    lstm_persistent<<<NB, NT, SMEM_BYTES>>>(
        u, wih0, whh0, bih0, bhh0, wih1, whh1, bih1, bhh1,
        fcw0, fcb0, fcw1, fcb1, out);
}

// round 5
// speedup vs baseline: 1.0533x; 1.0533x over previous
#include <cuda_runtime.h>

#define T_STEPS 512
#define Hdim    512
#define Bsz     256
#define INdim   8
#define NB      128   // CTAs, 1 per SM => co-resident => grid barrier safe
#define NT      512   // threads per CTA (16 warps for latency hiding)

// SMEM layout (float offsets)
#define WH0_OFF 0          // [512][32]  W_hh layer0 slice, k-major, rows interleaved
#define WI1_OFF 16384      // [512][32]  W_ih layer1 slice
#define WH1_OFF 32768      // [512][32]  W_hh layer1 slice
#define WI0_OFF 49152      // [8][32]    W_ih layer0 slice
#define B0_OFF  49408      // [32] combined bias layer0
#define B1_OFF  49440      // [32] combined bias layer1
#define SMEM_FLOATS 49472
#define SMEM_BYTES  (SMEM_FLOATS * 4)   // 197888 B < 227KB opt-in

// ---------------- global scratch (device statics: allocation-free) --------
__device__ float g_h0[2][Hdim][Bsz];   // layer0 h, double buffered, [col][batch]
__device__ float g_h1[2][Hdim][Bsz];   // layer1 h
__device__ float g_fch[256][Bsz];      // fc0 activations [row][batch]
__device__ unsigned g_arrive = 0;      // barrier arrive counter
__device__ unsigned g_gen    = 0;      // barrier release generation

// ---------------- f32x2 packed helpers ------------------------------------
__device__ __forceinline__ unsigned long long pack2(float x) {
    unsigned long long r;
    asm("mov.b64 %0, {%1,%2};" : "=l"(r)
        : "r"(__float_as_uint(x)), "r"(__float_as_uint(x)));
    return r;
}
__device__ __forceinline__ float2 unpack2(unsigned long long v) {
    unsigned lo, hi;
    asm("mov.b64 {%0,%1}, %2;" : "=r"(lo), "=r"(hi) : "l"(v));
    return make_float2(__uint_as_float(lo), __uint_as_float(hi));
}
__device__ __forceinline__ void fma2(unsigned long long& a,
                                     unsigned long long w,
                                     unsigned long long h) {
    asm("fma.rn.f32x2 %0, %1, %2, %0;" : "+l"(a) : "l"(w), "l"(h));
}
__device__ __forceinline__ float sigx(float x) { return 1.0f / (1.0f + __expf(-x)); }

// ---------------- software grid barrier (generation counter) --------------
__device__ __forceinline__ void grid_barrier() {
    __syncthreads();
    if (threadIdx.x == 0) {
        __threadfence();
        volatile unsigned* genp = &g_gen;
        unsigned snap = *genp;
        unsigned old = atomicAdd(&g_arrive, 1u);
        if (old == (unsigned)(NB - 1)) {
            g_arrive = 0u;       // safe: all other blocks are spinning on g_gen
            __threadfence();
            atomicAdd(&g_gen, 1u);
        } else {
            while (*genp == snap) { }
        }
        __threadfence();
    }
    __syncthreads();
}

// ---------------- one pipelined tick ---------------------------------------
// Tick t: layer0 step t (DOL0; recurrent term DWH0) and layer1 step t-1
// (DOL1; recurrent term DWH1). Each thread: 8 gate rows (4 f32x2) x 1 batch.
template<bool DOL0, bool DWH0, bool DOL1, bool DWH1>
__device__ __forceinline__ void tick(
    int t, int b, int rbase, int j0,
    const float* __restrict__ Wh0s, const float* __restrict__ Wi1s,
    const float* __restrict__ Wh1s, const float* __restrict__ Wi0s,
    const float* __restrict__ B0s,  const float* __restrict__ B1s,
    const float* __restrict__ u,
    float* c0, float* c1)
{
    const int pr  = (t - 1) & 1;   // parity of h0_{t-1}
    const int p1r = t & 1;         // parity of h1_{t-2}
    const int pw0 = t & 1;         // write parity for h0_t
    const int pw1 = (t - 1) & 1;   // write parity for h1_{t-1}

    unsigned long long a0[4], a1[4];

    if (DOL0) {
        const ulonglong2* bp = (const ulonglong2*)(B0s + rbase);
        ulonglong2 q0 = bp[0], q1 = bp[1];
        a0[0] = q0.x; a0[1] = q0.y; a0[2] = q1.x; a0[3] = q1.y;
        // input projection (IN = 8)
        const float4* xp = (const float4*)(u + ((size_t)b * T_STEPS + t) * INdim);
        float4 xa = xp[0], xb = xp[1];
        float xs[8] = {xa.x, xa.y, xa.z, xa.w, xb.x, xb.y, xb.z, xb.w};
        #pragma unroll
        for (int kk = 0; kk < INdim; ++kk) {
            const ulonglong2* wv = (const ulonglong2*)(Wi0s + kk * 32 + rbase);
            ulonglong2 w0 = wv[0], w1 = wv[1];
            unsigned long long hx = pack2(xs[kk]);
            fma2(a0[0], w0.x, hx); fma2(a0[1], w0.y, hx);
            fma2(a0[2], w1.x, hx); fma2(a0[3], w1.y, hx);
        }
    }
    if (DOL1) {
        const ulonglong2* bp = (const ulonglong2*)(B1s + rbase);
        ulonglong2 q0 = bp[0], q1 = bp[1];
        a1[0] = q0.x; a1[1] = q0.y; a1[2] = q1.x; a1[3] = q1.y;
    }

    if (DWH0 || DOL1) {
        const float* __restrict__ h0p = &g_h0[pr][0][0];
        const float* __restrict__ h1p = &g_h1[p1r][0][0];
        #pragma unroll 8
        for (int k = 0; k < Hdim; ++k) {
            float v = __ldcg(h0p + k * Bsz + b);
            unsigned long long hh = pack2(v);
            if (DWH0) {
                const ulonglong2* wv = (const ulonglong2*)(Wh0s + k * 32 + rbase);
                ulonglong2 w0 = wv[0], w1 = wv[1];
                fma2(a0[0], w0.x, hh); fma2(a0[1], w0.y, hh);
                fma2(a0[2], w1.x, hh); fma2(a0[3], w1.y, hh);
            }
            if (DOL1) {
                const ulonglong2* wv = (const ulonglong2*)(Wi1s + k * 32 + rbase);
                ulonglong2 w0 = wv[0], w1 = wv[1];
                fma2(a1[0], w0.x, hh); fma2(a1[1], w0.y, hh);
                fma2(a1[2], w1.x, hh); fma2(a1[3], w1.y, hh);
                if (DWH1) {
                    float g = __ldcg(h1p + k * Bsz + b);
                    unsigned long long gg = pack2(g);
                    const ulonglong2* uv = (const ulonglong2*)(Wh1s + k * 32 + rbase);
                    ulonglong2 u0 = uv[0], u1 = uv[1];
                    fma2(a1[0], u0.x, gg); fma2(a1[1], u0.y, gg);
                    fma2(a1[2], u1.x, gg); fma2(a1[3], u1.y, gg);
                }
            }
        }
    }

    // activations + cell update + h writes
    if (DOL0) {
        #pragma unroll
        for (int cc = 0; cc < 2; ++cc) {
            float2 ifp = unpack2(a0[cc * 2 + 0]);
            float2 gop = unpack2(a0[cc * 2 + 1]);
            float ig = sigx(ifp.x), fg = sigx(ifp.y);
            float gg = tanhf(gop.x), og = sigx(gop.y);
            float c = fg * c0[cc] + ig * gg;
            c0[cc] = c;
            float h = og * tanhf(c);
            int j = j0 + (rbase >> 2) + cc;
            __stcg(&g_h0[pw0][j][b], h);
        }
    }
    if (DOL1) {
        #pragma unroll
        for (int cc = 0; cc < 2; ++cc) {
            float2 ifp = unpack2(a1[cc * 2 + 0]);
            float2 gop = unpack2(a1[cc * 2 + 1]);
            float ig = sigx(ifp.x), fg = sigx(ifp.y);
            float gg = tanhf(gop.x), og = sigx(gop.y);
            float c = fg * c1[cc] + ig * gg;
            c1[cc] = c;
            float h = og * tanhf(c);
            int j = j0 + (rbase >> 2) + cc;
            __stcg(&g_h1[pw1][j][b], h);
        }
    }
}

// ---------------------------------------------------------------------------
__global__ void __launch_bounds__(NT, 1)
lstm_persistent(const float* __restrict__ u,
                const float* __restrict__ wih0, const float* __restrict__ whh0,
                const float* __restrict__ bih0, const float* __restrict__ bhh0,
                const float* __restrict__ wih1, const float* __restrict__ whh1,
                const float* __restrict__ bih1, const float* __restrict__ bhh1,
                const float* __restrict__ fcw0, const float* __restrict__ fcb0,
                const float* __restrict__ fcw1, const float* __restrict__ fcb1,
                float* __restrict__ out)
{
    extern __shared__ float smem[];
    float* Wh0s = smem + WH0_OFF;
    float* Wi1s = smem + WI1_OFF;
    float* Wh1s = smem + WH1_OFF;
    float* Wi0s = smem + WI0_OFF;
    float* B0s  = smem + B0_OFF;
    float* B1s  = smem + B1_OFF;

    const int tid = threadIdx.x;
    const int cg  = blockIdx.x >> 1;     // column group 0..63
    const int bg  = blockIdx.x & 1;      // batch half
    const int j0  = cg * 8;              // first hidden column of slice
    const int rq  = tid >> 7;            // row quarter 0..3 (8 gate rows each)
    const int bq  = tid & 127;           // batch lane 0..127
    const int rbase = rq * 8;
    const int b = bg * 128 + bq;         // this thread's batch element

    // ---- one-time weight staging into SMEM ----
    // local gate row r = jj*4 + g  (jj = col within slice, g = i,f,g,o)
    for (int i = tid; i < 32 * Hdim; i += NT) {
        int r = i & 31, k = i >> 5;
        int jj = r >> 2, g = r & 3;
        int grow = g * Hdim + j0 + jj;
        Wh0s[i] = whh0[grow * Hdim + k];
        Wi1s[i] = wih1[grow * Hdim + k];
        Wh1s[i] = whh1[grow * Hdim + k];
    }
    if (tid < 256) {
        int r = tid & 31, k = tid >> 5;  // covers [8][32] exactly
        int jj = r >> 2, g = r & 3;
        int grow = g * Hdim + j0 + jj;
        Wi0s[k * 32 + r] = wih0[grow * INdim + k];
    }
    if (tid < 32) {
        int jj = tid >> 2, g = tid & 3;
        int grow = g * Hdim + j0 + jj;
        B0s[tid] = bih0[grow] + bhh0[grow];
        B1s[tid] = bih1[grow] + bhh1[grow];
    }
    __syncthreads();

    float c0[2] = {0.f, 0.f};
    float c1[2] = {0.f, 0.f};

    // ---- pipelined time loop ----
    tick<true, false, false, false>(0, b, rbase, j0, Wh0s, Wi1s, Wh1s, Wi0s, B0s, B1s, u, c0, c1);
    grid_barrier();
    tick<true, true, true, false>(1, b, rbase, j0, Wh0s, Wi1s, Wh1s, Wi0s, B0s, B1s, u, c0, c1);
    grid_barrier();
    for (int t = 2; t < T_STEPS; ++t) {
        tick<true, true, true, true>(t, b, rbase, j0, Wh0s, Wi1s, Wh1s, Wi0s, B0s, B1s, u, c0, c1);
        grid_barrier();
    }
    tick<false, false, true, true>(T_STEPS, b, rbase, j0, Wh0s, Wi1s, Wh1s, Wi0s, B0s, B1s, u, c0, c1);
    grid_barrier();

    // ---- FC head stage A: fch[r][b] = tanh(fcw0[r,:] . h1_T[:,b] + fcb0[r]) ----
    {
        int gid = blockIdx.x * NT + tid;   // 0..65535 = 256 rows x 256 batches
        int r  = gid >> 8;
        int bb = gid & 255;
        const float* __restrict__ wrow  = fcw0 + (size_t)r * Hdim;
        const float* __restrict__ hbase = &g_h1[1][0][0];   // h1_{511} parity
        float acc = 0.f;
        #pragma unroll 8
        for (int k = 0; k < Hdim; ++k) {
            acc += __ldg(wrow + k) * __ldcg(hbase + k * Bsz + bb);
        }
        __stcg(&g_fch[r][bb], tanhf(acc + __ldg(fcb0 + r)));
    }
    grid_barrier();

    // ---- stage B (block 0): final 2-wide FC + affine ----
    if (blockIdx.x == 0 && tid < 256) {
        int bb = tid;
        float s0 = __ldg(fcb1 + 0), s1 = __ldg(fcb1 + 1);
        #pragma unroll 8
        for (int k = 0; k < 256; ++k) {
            float v = __ldcg(&g_fch[k][bb]);
            s0 += v * __ldg(fcw1 + k);
            s1 += v * __ldg(fcw1 + 256 + k);
        }
        const float scale = 0.5f * (4.2f - 2.5f);
        out[bb * 2 + 0] = (s0 + 1.0f) * scale + 2.5f;
        out[bb * 2 + 1] = (s1 + 1.0f) * scale + 2.5f;
    }
}

// ---------------------------------------------------------------------------
extern "C" void kernel_launch(void* const* d_in, const int* in_sizes, int n_in,
                              void* d_out, int out_size) {
    (void)in_sizes; (void)n_in; (void)out_size;
    const float* u    = (const float*)d_in[0];
    const float* wih0 = (const float*)d_in[1];
    const float* whh0 = (const float*)d_in[2];
    const float* bih0 = (const float*)d_in[3];
    const float* bhh0 = (const float*)d_in[4];
    const float* wih1 = (const float*)d_in[5];
    const float* whh1 = (const float*)d_in[6];
    const float* bih1 = (const float*)d_in[7];
    const float* bhh1 = (const float*)d_in[8];
    const float* fcw0 = (const float*)d_in[9];
    const float* fcb0 = (const float*)d_in[10];
    const float* fcw1 = (const float*)d_in[11];
    const float* fcb1 = (const float*)d_in[12];
    float* out = (float*)d_out;

    cudaFuncSetAttribute(lstm_persistent,
                         cudaFuncAttributeMaxDynamicSharedMemorySize, SMEM_BYTES);
    lstm_persistent<<<NB, NT, SMEM_BYTES>>>(
        u, wih0, whh0, bih0, bhh0, wih1, whh1, bih1, bhh1,
        fcw0, fcb0, fcw1, fcb1, out);
}

// round 6
// speedup vs baseline: 1.0562x; 1.0028x over previous
#include <cuda_runtime.h>

#define T_STEPS 512
#define Hdim    512
#define Bsz     256
#define INdim   8
#define NB      128   // CTAs, 1 per SM => co-resident => grid barrier safe
#define NT      512   // threads per CTA (16 warps for latency hiding)

// SMEM layout (float offsets)
#define WH0_OFF 0          // [512][32]  W_hh layer0 slice, k-major, rows interleaved
#define WI1_OFF 16384      // [512][32]  W_ih layer1 slice
#define WH1_OFF 32768      // [512][32]  W_hh layer1 slice
#define WI0_OFF 49152      // [8][32]    W_ih layer0 slice
#define B0_OFF  49408      // [32] combined bias layer0
#define B1_OFF  49440      // [32] combined bias layer1
#define SMEM_FLOATS 49472
#define SMEM_BYTES  (SMEM_FLOATS * 4)   // 197888 B < 227KB opt-in

// ---------------- global scratch (device statics: allocation-free) --------
__device__ float g_h0[2][Hdim][Bsz];   // layer0 h, double buffered, [col][batch]
__device__ float g_h1[2][Hdim][Bsz];   // layer1 h
__device__ float g_fch[256][Bsz];      // fc0 activations [row][batch]
__device__ unsigned g_arrive = 0;      // barrier arrive counter
__device__ unsigned g_gen    = 0;      // barrier release generation

// ---------------- f32x2 packed helpers ------------------------------------
__device__ __forceinline__ unsigned long long pack2(float x) {
    unsigned long long r;
    asm("mov.b64 %0, {%1,%2};" : "=l"(r)
        : "r"(__float_as_uint(x)), "r"(__float_as_uint(x)));
    return r;
}
__device__ __forceinline__ float2 unpack2(unsigned long long v) {
    unsigned lo, hi;
    asm("mov.b64 {%0,%1}, %2;" : "=r"(lo), "=r"(hi) : "l"(v));
    return make_float2(__uint_as_float(lo), __uint_as_float(hi));
}
__device__ __forceinline__ void fma2(unsigned long long& a,
                                     unsigned long long w,
                                     unsigned long long h) {
    asm("fma.rn.f32x2 %0, %1, %2, %0;" : "+l"(a) : "l"(w), "l"(h));
}
__device__ __forceinline__ float sigx(float x) { return 1.0f / (1.0f + __expf(-x)); }

// ---------------- software grid barrier (generation counter) --------------
__device__ __forceinline__ void grid_barrier() {
    __syncthreads();
    if (threadIdx.x == 0) {
        __threadfence();
        volatile unsigned* genp = &g_gen;
        unsigned snap = *genp;
        unsigned old = atomicAdd(&g_arrive, 1u);
        if (old == (unsigned)(NB - 1)) {
            g_arrive = 0u;       // safe: all other blocks are spinning on g_gen
            __threadfence();
            atomicAdd(&g_gen, 1u);
        } else {
            while (*genp == snap) { }
        }
        __threadfence();
    }
    __syncthreads();
}

// ---------------- one pipelined tick ---------------------------------------
// Tick t: layer0 step t (DOL0; recurrent term DWH0) and layer1 step t-1
// (DOL1; recurrent term DWH1). Each thread: 8 gate rows (4 f32x2) x 1 batch.
template<bool DOL0, bool DWH0, bool DOL1, bool DWH1>
__device__ __forceinline__ void tick(
    int t, int b, int rbase, int j0,
    const float* __restrict__ Wh0s, const float* __restrict__ Wi1s,
    const float* __restrict__ Wh1s, const float* __restrict__ Wi0s,
    const float* __restrict__ B0s,  const float* __restrict__ B1s,
    const float* __restrict__ u,
    float* c0, float* c1)
{
    const int pr  = (t - 1) & 1;   // parity of h0_{t-1}
    const int p1r = t & 1;         // parity of h1_{t-2}
    const int pw0 = t & 1;         // write parity for h0_t
    const int pw1 = (t - 1) & 1;   // write parity for h1_{t-1}

    unsigned long long a0[4], a1[4];

    if (DOL0) {
        const ulonglong2* bp = (const ulonglong2*)(B0s + rbase);
        ulonglong2 q0 = bp[0], q1 = bp[1];
        a0[0] = q0.x; a0[1] = q0.y; a0[2] = q1.x; a0[3] = q1.y;
        // input projection (IN = 8)
        const float4* xp = (const float4*)(u + ((size_t)b * T_STEPS + t) * INdim);
        float4 xa = xp[0], xb = xp[1];
        float xs[8] = {xa.x, xa.y, xa.z, xa.w, xb.x, xb.y, xb.z, xb.w};
        #pragma unroll
        for (int kk = 0; kk < INdim; ++kk) {
            const ulonglong2* wv = (const ulonglong2*)(Wi0s + kk * 32 + rbase);
            ulonglong2 w0 = wv[0], w1 = wv[1];
            unsigned long long hx = pack2(xs[kk]);
            fma2(a0[0], w0.x, hx); fma2(a0[1], w0.y, hx);
            fma2(a0[2], w1.x, hx); fma2(a0[3], w1.y, hx);
        }
    }
    if (DOL1) {
        const ulonglong2* bp = (const ulonglong2*)(B1s + rbase);
        ulonglong2 q0 = bp[0], q1 = bp[1];
        a1[0] = q0.x; a1[1] = q0.y; a1[2] = q1.x; a1[3] = q1.y;
    }

    if (DWH0 || DOL1) {
        const float* __restrict__ h0p = &g_h0[pr][0][0];
        const float* __restrict__ h1p = &g_h1[p1r][0][0];
        #pragma unroll 8
        for (int k = 0; k < Hdim; ++k) {
            float v = __ldcg(h0p + k * Bsz + b);
            unsigned long long hh = pack2(v);
            if (DWH0) {
                const ulonglong2* wv = (const ulonglong2*)(Wh0s + k * 32 + rbase);
                ulonglong2 w0 = wv[0], w1 = wv[1];
                fma2(a0[0], w0.x, hh); fma2(a0[1], w0.y, hh);
                fma2(a0[2], w1.x, hh); fma2(a0[3], w1.y, hh);
            }
            if (DOL1) {
                const ulonglong2* wv = (const ulonglong2*)(Wi1s + k * 32 + rbase);
                ulonglong2 w0 = wv[0], w1 = wv[1];
                fma2(a1[0], w0.x, hh); fma2(a1[1], w0.y, hh);
                fma2(a1[2], w1.x, hh); fma2(a1[3], w1.y, hh);
                if (DWH1) {
                    float g = __ldcg(h1p + k * Bsz + b);
                    unsigned long long gg = pack2(g);
                    const ulonglong2* uv = (const ulonglong2*)(Wh1s + k * 32 + rbase);
                    ulonglong2 u0 = uv[0], u1 = uv[1];
                    fma2(a1[0], u0.x, gg); fma2(a1[1], u0.y, gg);
                    fma2(a1[2], u1.x, gg); fma2(a1[3], u1.y, gg);
                }
            }
        }
    }

    // activations + cell update + h writes
    if (DOL0) {
        #pragma unroll
        for (int cc = 0; cc < 2; ++cc) {
            float2 ifp = unpack2(a0[cc * 2 + 0]);
            float2 gop = unpack2(a0[cc * 2 + 1]);
            float ig = sigx(ifp.x), fg = sigx(ifp.y);
            float gg = tanhf(gop.x), og = sigx(gop.y);
            float c = fg * c0[cc] + ig * gg;
            c0[cc] = c;
            float h = og * tanhf(c);
            int j = j0 + (rbase >> 2) + cc;
            __stcg(&g_h0[pw0][j][b], h);
        }
    }
    if (DOL1) {
        #pragma unroll
        for (int cc = 0; cc < 2; ++cc) {
            float2 ifp = unpack2(a1[cc * 2 + 0]);
            float2 gop = unpack2(a1[cc * 2 + 1]);
            float ig = sigx(ifp.x), fg = sigx(ifp.y);
            float gg = tanhf(gop.x), og = sigx(gop.y);
            float c = fg * c1[cc] + ig * gg;
            c1[cc] = c;
            float h = og * tanhf(c);
            int j = j0 + (rbase >> 2) + cc;
            __stcg(&g_h1[pw1][j][b], h);
        }
    }
}

// ---------------------------------------------------------------------------
__global__ void __launch_bounds__(NT, 1)
lstm_persistent(const float* __restrict__ u,
                const float* __restrict__ wih0, const float* __restrict__ whh0,
                const float* __restrict__ bih0, const float* __restrict__ bhh0,
                const float* __restrict__ wih1, const float* __restrict__ whh1,
                const float* __restrict__ bih1, const float* __restrict__ bhh1,
                const float* __restrict__ fcw0, const float* __restrict__ fcb0,
                const float* __restrict__ fcw1, const float* __restrict__ fcb1,
                float* __restrict__ out)
{
    extern __shared__ float smem[];
    float* Wh0s = smem + WH0_OFF;
    float* Wi1s = smem + WI1_OFF;
    float* Wh1s = smem + WH1_OFF;
    float* Wi0s = smem + WI0_OFF;
    float* B0s  = smem + B0_OFF;
    float* B1s  = smem + B1_OFF;

    const int tid = threadIdx.x;
    const int cg  = blockIdx.x >> 1;     // column group 0..63
    const int bg  = blockIdx.x & 1;      // batch half
    const int j0  = cg * 8;              // first hidden column of slice
    const int rq  = tid >> 7;            // row quarter 0..3 (8 gate rows each)
    const int bq  = tid & 127;           // batch lane 0..127
    const int rbase = rq * 8;
    const int b = bg * 128 + bq;         // this thread's batch element

    // ---- one-time weight staging into SMEM ----
    // local gate row r = jj*4 + g  (jj = col within slice, g = i,f,g,o)
    for (int i = tid; i < 32 * Hdim; i += NT) {
        int r = i & 31, k = i >> 5;
        int jj = r >> 2, g = r & 3;
        int grow = g * Hdim + j0 + jj;
        Wh0s[i] = whh0[grow * Hdim + k];
        Wi1s[i] = wih1[grow * Hdim + k];
        Wh1s[i] = whh1[grow * Hdim + k];
    }
    if (tid < 256) {
        int r = tid & 31, k = tid >> 5;  // covers [8][32] exactly
        int jj = r >> 2, g = r & 3;
        int grow = g * Hdim + j0 + jj;
        Wi0s[k * 32 + r] = wih0[grow * INdim + k];
    }
    if (tid < 32) {
        int jj = tid >> 2, g = tid & 3;
        int grow = g * Hdim + j0 + jj;
        B0s[tid] = bih0[grow] + bhh0[grow];
        B1s[tid] = bih1[grow] + bhh1[grow];
    }
    __syncthreads();

    float c0[2] = {0.f, 0.f};
    float c1[2] = {0.f, 0.f};

    // ---- pipelined time loop ----
    tick<true, false, false, false>(0, b, rbase, j0, Wh0s, Wi1s, Wh1s, Wi0s, B0s, B1s, u, c0, c1);
    grid_barrier();
    tick<true, true, true, false>(1, b, rbase, j0, Wh0s, Wi1s, Wh1s, Wi0s, B0s, B1s, u, c0, c1);
    grid_barrier();
    for (int t = 2; t < T_STEPS; ++t) {
        tick<true, true, true, true>(t, b, rbase, j0, Wh0s, Wi1s, Wh1s, Wi0s, B0s, B1s, u, c0, c1);
        grid_barrier();
    }
    tick<false, false, true, true>(T_STEPS, b, rbase, j0, Wh0s, Wi1s, Wh1s, Wi0s, B0s, B1s, u, c0, c1);
    grid_barrier();

    // ---- FC head stage A: fch[r][b] = tanh(fcw0[r,:] . h1_T[:,b] + fcb0[r]) ----
    {
        int gid = blockIdx.x * NT + tid;   // 0..65535 = 256 rows x 256 batches
        int r  = gid >> 8;
        int bb = gid & 255;
        const float* __restrict__ wrow  = fcw0 + (size_t)r * Hdim;
        const float* __restrict__ hbase = &g_h1[1][0][0];   // h1_{511} parity
        float acc = 0.f;
        #pragma unroll 8
        for (int k = 0; k < Hdim; ++k) {
            acc += __ldg(wrow + k) * __ldcg(hbase + k * Bsz + bb);
        }
        __stcg(&g_fch[r][bb], tanhf(acc + __ldg(fcb0 + r)));
    }
    grid_barrier();

    // ---- stage B (block 0): final 2-wide FC + affine ----
    if (blockIdx.x == 0 && tid < 256) {
        int bb = tid;
        float s0 = __ldg(fcb1 + 0), s1 = __ldg(fcb1 + 1);
        #pragma unroll 8
        for (int k = 0; k < 256; ++k) {
            float v = __ldcg(&g_fch[k][bb]);
            s0 += v * __ldg(fcw1 + k);
            s1 += v * __ldg(fcw1 + 256 + k);
        }
        const float scale = 0.5f * (4.2f - 2.5f);
        out[bb * 2 + 0] = (s0 + 1.0f) * scale + 2.5f;
        out[bb * 2 + 1] = (s1 + 1.0f) * scale + 2.5f;
    }
}

// ---------------------------------------------------------------------------
extern "C" void kernel_launch(void* const* d_in, const int* in_sizes, int n_in,
                              void* d_out, int out_size) {
    (void)in_sizes; (void)n_in; (void)out_size;
    const float* u    = (const float*)d_in[0];
    const float* wih0 = (const float*)d_in[1];
    const float* whh0 = (const float*)d_in[2];
    const float* bih0 = (const float*)d_in[3];
    const float* bhh0 = (const float*)d_in[4];
    const float* wih1 = (const float*)d_in[5];
    const float* whh1 = (const float*)d_in[6];
    const float* bih1 = (const float*)d_in[7];
    const float* bhh1 = (const float*)d_in[8];
    const float* fcw0 = (const float*)d_in[9];
    const float* fcb0 = (const float*)d_in[10];
    const float* fcw1 = (const float*)d_in[11];
    const float* fcb1 = (const float*)d_in[12];
    float* out = (float*)d_out;

    cudaFuncSetAttribute(lstm_persistent,
                         cudaFuncAttributeMaxDynamicSharedMemorySize, SMEM_BYTES);
    lstm_persistent<<<NB, NT, SMEM_BYTES>>>(
        u, wih0, whh0, bih0, bhh0, wih1, whh1, bih1, bhh1,
        fcw0, fcb0, fcw1, fcb1, out);
}

// round 7
// speedup vs baseline: 1.0573x; 1.0011x over previous
#include <cuda_runtime.h>

#define T_STEPS 512
#define Hdim    512
#define Bsz     256
#define INdim   8
#define NB      128   // CTAs, 1 per SM => co-resident => grid barrier safe
#define NT      512   // threads per CTA (16 warps for latency hiding)

// SMEM layout (float offsets)
#define WH0_OFF 0          // [512][32]  W_hh layer0 slice, k-major, rows interleaved
#define WI1_OFF 16384      // [512][32]  W_ih layer1 slice
#define WH1_OFF 32768      // [512][32]  W_hh layer1 slice
#define WI0_OFF 49152      // [8][32]    W_ih layer0 slice
#define B0_OFF  49408      // [32] combined bias layer0
#define B1_OFF  49440      // [32] combined bias layer1
#define SMEM_FLOATS 49472
#define SMEM_BYTES  (SMEM_FLOATS * 4)   // 197888 B < 227KB opt-in

// ---------------- global scratch (device statics: allocation-free) --------
__device__ float g_h0[2][Hdim][Bsz];   // layer0 h, double buffered, [col][batch]
__device__ float g_h1[2][Hdim][Bsz];   // layer1 h
__device__ float g_fch[256][Bsz];      // fc0 activations [row][batch]
__device__ unsigned g_arrive = 0;      // barrier arrive counter
__device__ unsigned g_gen    = 0;      // barrier release generation

// ---------------- f32x2 packed helpers ------------------------------------
__device__ __forceinline__ unsigned long long pack2(float x) {
    unsigned long long r;
    asm("mov.b64 %0, {%1,%2};" : "=l"(r)
        : "r"(__float_as_uint(x)), "r"(__float_as_uint(x)));
    return r;
}
__device__ __forceinline__ float2 unpack2(unsigned long long v) {
    unsigned lo, hi;
    asm("mov.b64 {%0,%1}, %2;" : "=r"(lo), "=r"(hi) : "l"(v));
    return make_float2(__uint_as_float(lo), __uint_as_float(hi));
}
__device__ __forceinline__ void fma2(unsigned long long& a,
                                     unsigned long long w,
                                     unsigned long long h) {
    asm("fma.rn.f32x2 %0, %1, %2, %0;" : "+l"(a) : "l"(w), "l"(h));
}
__device__ __forceinline__ float sigx(float x) { return 1.0f / (1.0f + __expf(-x)); }

// ---------------- software grid barrier (generation counter) --------------
__device__ __forceinline__ void grid_barrier() {
    __syncthreads();
    if (threadIdx.x == 0) {
        __threadfence();
        volatile unsigned* genp = &g_gen;
        unsigned snap = *genp;
        unsigned old = atomicAdd(&g_arrive, 1u);
        if (old == (unsigned)(NB - 1)) {
            g_arrive = 0u;       // safe: all other blocks are spinning on g_gen
            __threadfence();
            atomicAdd(&g_gen, 1u);
        } else {
            while (*genp == snap) { }
        }
        __threadfence();
    }
    __syncthreads();
}

// ---------------- one pipelined tick ---------------------------------------
// Tick t: layer0 step t (DOL0; recurrent term DWH0) and layer1 step t-1
// (DOL1; recurrent term DWH1). Each thread: 8 gate rows (4 f32x2) x 1 batch.
template<bool DOL0, bool DWH0, bool DOL1, bool DWH1>
__device__ __forceinline__ void tick(
    int t, int b, int rbase, int j0,
    const float* __restrict__ Wh0s, const float* __restrict__ Wi1s,
    const float* __restrict__ Wh1s, const float* __restrict__ Wi0s,
    const float* __restrict__ B0s,  const float* __restrict__ B1s,
    const float* __restrict__ u,
    float* c0, float* c1)
{
    const int pr  = (t - 1) & 1;   // parity of h0_{t-1}
    const int p1r = t & 1;         // parity of h1_{t-2}
    const int pw0 = t & 1;         // write parity for h0_t
    const int pw1 = (t - 1) & 1;   // write parity for h1_{t-1}

    unsigned long long a0[4], a1[4];

    if (DOL0) {
        const ulonglong2* bp = (const ulonglong2*)(B0s + rbase);
        ulonglong2 q0 = bp[0], q1 = bp[1];
        a0[0] = q0.x; a0[1] = q0.y; a0[2] = q1.x; a0[3] = q1.y;
        // input projection (IN = 8)
        const float4* xp = (const float4*)(u + ((size_t)b * T_STEPS + t) * INdim);
        float4 xa = xp[0], xb = xp[1];
        float xs[8] = {xa.x, xa.y, xa.z, xa.w, xb.x, xb.y, xb.z, xb.w};
        #pragma unroll
        for (int kk = 0; kk < INdim; ++kk) {
            const ulonglong2* wv = (const ulonglong2*)(Wi0s + kk * 32 + rbase);
            ulonglong2 w0 = wv[0], w1 = wv[1];
            unsigned long long hx = pack2(xs[kk]);
            fma2(a0[0], w0.x, hx); fma2(a0[1], w0.y, hx);
            fma2(a0[2], w1.x, hx); fma2(a0[3], w1.y, hx);
        }
    }
    if (DOL1) {
        const ulonglong2* bp = (const ulonglong2*)(B1s + rbase);
        ulonglong2 q0 = bp[0], q1 = bp[1];
        a1[0] = q0.x; a1[1] = q0.y; a1[2] = q1.x; a1[3] = q1.y;
    }

    if (DWH0 || DOL1) {
        const float* __restrict__ h0p = &g_h0[pr][0][0];
        const float* __restrict__ h1p = &g_h1[p1r][0][0];
        #pragma unroll 8
        for (int k = 0; k < Hdim; ++k) {
            float v = __ldcg(h0p + k * Bsz + b);
            unsigned long long hh = pack2(v);
            if (DWH0) {
                const ulonglong2* wv = (const ulonglong2*)(Wh0s + k * 32 + rbase);
                ulonglong2 w0 = wv[0], w1 = wv[1];
                fma2(a0[0], w0.x, hh); fma2(a0[1], w0.y, hh);
                fma2(a0[2], w1.x, hh); fma2(a0[3], w1.y, hh);
            }
            if (DOL1) {
                const ulonglong2* wv = (const ulonglong2*)(Wi1s + k * 32 + rbase);
                ulonglong2 w0 = wv[0], w1 = wv[1];
                fma2(a1[0], w0.x, hh); fma2(a1[1], w0.y, hh);
                fma2(a1[2], w1.x, hh); fma2(a1[3], w1.y, hh);
                if (DWH1) {
                    float g = __ldcg(h1p + k * Bsz + b);
                    unsigned long long gg = pack2(g);
                    const ulonglong2* uv = (const ulonglong2*)(Wh1s + k * 32 + rbase);
                    ulonglong2 u0 = uv[0], u1 = uv[1];
                    fma2(a1[0], u0.x, gg); fma2(a1[1], u0.y, gg);
                    fma2(a1[2], u1.x, gg); fma2(a1[3], u1.y, gg);
                }
            }
        }
    }

    // activations + cell update + h writes
    if (DOL0) {
        #pragma unroll
        for (int cc = 0; cc < 2; ++cc) {
            float2 ifp = unpack2(a0[cc * 2 + 0]);
            float2 gop = unpack2(a0[cc * 2 + 1]);
            float ig = sigx(ifp.x), fg = sigx(ifp.y);
            float gg = tanhf(gop.x), og = sigx(gop.y);
            float c = fg * c0[cc] + ig * gg;
            c0[cc] = c;
            float h = og * tanhf(c);
            int j = j0 + (rbase >> 2) + cc;
            __stcg(&g_h0[pw0][j][b], h);
        }
    }
    if (DOL1) {
        #pragma unroll
        for (int cc = 0; cc < 2; ++cc) {
            float2 ifp = unpack2(a1[cc * 2 + 0]);
            float2 gop = unpack2(a1[cc * 2 + 1]);
            float ig = sigx(ifp.x), fg = sigx(ifp.y);
            float gg = tanhf(gop.x), og = sigx(gop.y);
            float c = fg * c1[cc] + ig * gg;
            c1[cc] = c;
            float h = og * tanhf(c);
            int j = j0 + (rbase >> 2) + cc;
            __stcg(&g_h1[pw1][j][b], h);
        }
    }
}

// ---------------------------------------------------------------------------
__global__ void __launch_bounds__(NT, 1)
lstm_persistent(const float* __restrict__ u,
                const float* __restrict__ wih0, const float* __restrict__ whh0,
                const float* __restrict__ bih0, const float* __restrict__ bhh0,
                const float* __restrict__ wih1, const float* __restrict__ whh1,
                const float* __restrict__ bih1, const float* __restrict__ bhh1,
                const float* __restrict__ fcw0, const float* __restrict__ fcb0,
                const float* __restrict__ fcw1, const float* __restrict__ fcb1,
                float* __restrict__ out)
{
    extern __shared__ float smem[];
    float* Wh0s = smem + WH0_OFF;
    float* Wi1s = smem + WI1_OFF;
    float* Wh1s = smem + WH1_OFF;
    float* Wi0s = smem + WI0_OFF;
    float* B0s  = smem + B0_OFF;
    float* B1s  = smem + B1_OFF;

    const int tid = threadIdx.x;
    const int cg  = blockIdx.x >> 1;     // column group 0..63
    const int bg  = blockIdx.x & 1;      // batch half
    const int j0  = cg * 8;              // first hidden column of slice
    const int rq  = tid >> 7;            // row quarter 0..3 (8 gate rows each)
    const int bq  = tid & 127;           // batch lane 0..127
    const int rbase = rq * 8;
    const int b = bg * 128 + bq;         // this thread's batch element

    // ---- one-time weight staging into SMEM ----
    // local gate row r = jj*4 + g  (jj = col within slice, g = i,f,g,o)
    for (int i = tid; i < 32 * Hdim; i += NT) {
        int r = i & 31, k = i >> 5;
        int jj = r >> 2, g = r & 3;
        int grow = g * Hdim + j0 + jj;
        Wh0s[i] = whh0[grow * Hdim + k];
        Wi1s[i] = wih1[grow * Hdim + k];
        Wh1s[i] = whh1[grow * Hdim + k];
    }
    if (tid < 256) {
        int r = tid & 31, k = tid >> 5;  // covers [8][32] exactly
        int jj = r >> 2, g = r & 3;
        int grow = g * Hdim + j0 + jj;
        Wi0s[k * 32 + r] = wih0[grow * INdim + k];
    }
    if (tid < 32) {
        int jj = tid >> 2, g = tid & 3;
        int grow = g * Hdim + j0 + jj;
        B0s[tid] = bih0[grow] + bhh0[grow];
        B1s[tid] = bih1[grow] + bhh1[grow];
    }
    __syncthreads();

    float c0[2] = {0.f, 0.f};
    float c1[2] = {0.f, 0.f};

    // ---- pipelined time loop ----
    tick<true, false, false, false>(0, b, rbase, j0, Wh0s, Wi1s, Wh1s, Wi0s, B0s, B1s, u, c0, c1);
    grid_barrier();
    tick<true, true, true, false>(1, b, rbase, j0, Wh0s, Wi1s, Wh1s, Wi0s, B0s, B1s, u, c0, c1);
    grid_barrier();
    for (int t = 2; t < T_STEPS; ++t) {
        tick<true, true, true, true>(t, b, rbase, j0, Wh0s, Wi1s, Wh1s, Wi0s, B0s, B1s, u, c0, c1);
        grid_barrier();
    }
    tick<false, false, true, true>(T_STEPS, b, rbase, j0, Wh0s, Wi1s, Wh1s, Wi0s, B0s, B1s, u, c0, c1);
    grid_barrier();

    // ---- FC head stage A: fch[r][b] = tanh(fcw0[r,:] . h1_T[:,b] + fcb0[r]) ----
    {
        int gid = blockIdx.x * NT + tid;   // 0..65535 = 256 rows x 256 batches
        int r  = gid >> 8;
        int bb = gid & 255;
        const float* __restrict__ wrow  = fcw0 + (size_t)r * Hdim;
        const float* __restrict__ hbase = &g_h1[1][0][0];   // h1_{511} parity
        float acc = 0.f;
        #pragma unroll 8
        for (int k = 0; k < Hdim; ++k) {
            acc += __ldg(wrow + k) * __ldcg(hbase + k * Bsz + bb);
        }
        __stcg(&g_fch[r][bb], tanhf(acc + __ldg(fcb0 + r)));
    }
    grid_barrier();

    // ---- stage B (block 0): final 2-wide FC + affine ----
    if (blockIdx.x == 0 && tid < 256) {
        int bb = tid;
        float s0 = __ldg(fcb1 + 0), s1 = __ldg(fcb1 + 1);
        #pragma unroll 8
        for (int k = 0; k < 256; ++k) {
            float v = __ldcg(&g_fch[k][bb]);
            s0 += v * __ldg(fcw1 + k);
            s1 += v * __ldg(fcw1 + 256 + k);
        }
        const float scale = 0.5f * (4.2f - 2.5f);
        out[bb * 2 + 0] = (s0 + 1.0f) * scale + 2.5f;
        out[bb * 2 + 1] = (s1 + 1.0f) * scale + 2.5f;
    }
}

// ---------------------------------------------------------------------------
extern "C" void kernel_launch(void* const* d_in, const int* in_sizes, int n_in,
                              void* d_out, int out_size) {
    (void)in_sizes; (void)n_in; (void)out_size;
    const float* u    = (const float*)d_in[0];
    const float* wih0 = (const float*)d_in[1];
    const float* whh0 = (const float*)d_in[2];
    const float* bih0 = (const float*)d_in[3];
    const float* bhh0 = (const float*)d_in[4];
    const float* wih1 = (const float*)d_in[5];
    const float* whh1 = (const float*)d_in[6];
    const float* bih1 = (const float*)d_in[7];
    const float* bhh1 = (const float*)d_in[8];
    const float* fcw0 = (const float*)d_in[9];
    const float* fcb0 = (const float*)d_in[10];
    const float* fcw1 = (const float*)d_in[11];
    const float* fcb1 = (const float*)d_in[12];
    float* out = (float*)d_out;

    cudaFuncSetAttribute(lstm_persistent,
                         cudaFuncAttributeMaxDynamicSharedMemorySize, SMEM_BYTES);
    lstm_persistent<<<NB, NT, SMEM_BYTES>>>(
        u, wih0, whh0, bih0, bhh0, wih1, whh1, bih1, bhh1,
        fcw0, fcb0, fcw1, fcb1, out);
}

// round 10
// speedup vs baseline: 1.9261x; 1.8217x over previous
#include <cuda_runtime.h>
#include <cuda_bf16.h>

#define T_STEPS 512
#define NCTA    96
#define NT      512

// ---------------- SMEM byte offsets (from 128B-aligned base) ---------------
#define SM_AHI   0                         // 64x512 bf16, swizzled (64KB)
#define SM_ALO   65536                     // 64KB
#define SM_BBUF(bs) (131072 + (bs)*40960)  // 2 bufs x (hi 20480 + lo 20480)
#define SM_HSTG  131072                    // reused in epilogue: 16 x 256 u32
#define SM_BIAS  212992                    // 64 f32
#define SM_WI0   213248                    // 64x8 f32
#define SMEM_ALLOC (215296 + 256)

// ---------------- global scratch -------------------------------------------
__device__ __nv_bfloat16 g_hhi[2][2][256][512];   // [layer][parity][b][k]
__device__ __nv_bfloat16 g_hlo[2][2][256][512];
__device__ float g_Dp[32][64][256];               // Whh1 partials
__device__ float g_fch[256][256];                 // [row][b]
__device__ unsigned g_arrive = 0;
__device__ unsigned g_gen    = 0;

__device__ __forceinline__ float sigx(float x) { return 1.0f / (1.0f + __expf(-x)); }

__device__ __forceinline__ unsigned smem_u32(const void* p) {
    unsigned a;
    asm("{ .reg .u64 t; cvta.to.shared.u64 t, %1; cvt.u32.u64 %0, t; }" : "=r"(a) : "l"(p));
    return a;
}
__device__ __forceinline__ void ldm_x4(unsigned* r, unsigned addr) {
    asm volatile("ldmatrix.sync.aligned.m8n8.x4.shared.b16 {%0,%1,%2,%3}, [%4];"
        : "=r"(r[0]), "=r"(r[1]), "=r"(r[2]), "=r"(r[3]) : "r"(addr));
}
// B tile is n-major (row = batch column, k contiguous) => NON-trans ldmatrix
// yields the m16n8k16 B fragment directly. (.trans here was the R8 bug.)
__device__ __forceinline__ void ldm_x2(unsigned* r, unsigned addr) {
    asm volatile("ldmatrix.sync.aligned.m8n8.x2.shared.b16 {%0,%1}, [%2];"
        : "=r"(r[0]), "=r"(r[1]) : "r"(addr));
}
__device__ __forceinline__ void mma16816(float* c, const unsigned* a, const unsigned* b) {
    asm volatile(
        "mma.sync.aligned.m16n8k16.row.col.f32.bf16.bf16.f32 "
        "{%0,%1,%2,%3}, {%4,%5,%6,%7}, {%8,%9}, {%0,%1,%2,%3};"
        : "+f"(c[0]), "+f"(c[1]), "+f"(c[2]), "+f"(c[3])
        : "r"(a[0]), "r"(a[1]), "r"(a[2]), "r"(a[3]), "r"(b[0]), "r"(b[1]));
}
__device__ __forceinline__ void cpasync16(unsigned dst, const void* src) {
    asm volatile("cp.async.cg.shared.global [%0], [%1], 16;" :: "r"(dst), "l"(src));
}

// ---------------- grid barrier (generation counter) ------------------------
__device__ __forceinline__ void grid_barrier() {
    __syncthreads();
    if (threadIdx.x == 0) {
        __threadfence();
        volatile unsigned* genp = &g_gen;
        unsigned snap = *genp;
        unsigned old = atomicAdd(&g_arrive, 1u);
        if (old == (unsigned)(NCTA - 1)) {
            g_arrive = 0u;
            __threadfence();
            atomicAdd(&g_gen, 1u);
        } else {
            while (*genp == snap) { }
        }
        __threadfence();
    }
    __syncthreads();
}

// ---------------------------------------------------------------------------
__global__ void __launch_bounds__(NT, 1)
lstm_hmma(const float* __restrict__ u,
          const float* __restrict__ wih0, const float* __restrict__ whh0,
          const float* __restrict__ bih0, const float* __restrict__ bhh0,
          const float* __restrict__ wih1, const float* __restrict__ whh1,
          const float* __restrict__ bih1, const float* __restrict__ bhh1,
          const float* __restrict__ fcw0, const float* __restrict__ fcb0,
          const float* __restrict__ fcw1, const float* __restrict__ fcb1,
          float* __restrict__ out)
{
    extern __shared__ char smraw[];
    char* sm = (char*)((((unsigned long long)(size_t)smraw) + 127) & ~127ULL);
    const unsigned smb = smem_u32(sm);
    const int tid = threadIdx.x, wid = tid >> 5, l = tid & 31;
    const int cta = blockIdx.x;

    // roles: 0 = L0 (Whh0), 1 = Wih1, 2 = Whh1
    const int role = cta >> 5;
    const int m    = cta & 31;          // row-slice: units j0 = m*16
    const float* Asrc = (role == 0) ? whh0 : (role == 1) ? wih1 : whh1;

    // ---- one-time A staging: bf16 hi/lo, row r = g*16+jj, XOR-16B-chunk swizzle
    for (int idx = tid; idx < 64 * 512; idx += NT) {
        int r = idx >> 9, k = idx & 511;
        int grow = (r >> 4) * 512 + m * 16 + (r & 15);
        float w = Asrc[(size_t)grow * 512 + k];
        __nv_bfloat16 hi = __float2bfloat16(w);
        __nv_bfloat16 lo = __float2bfloat16(w - __bfloat162float(hi));
        int chunk = (k >> 3) ^ (r & 7);
        int byte  = r * 1024 + (chunk << 4) + (k & 7) * 2;
        *(__nv_bfloat16*)(sm + SM_AHI + byte) = hi;
        *(__nv_bfloat16*)(sm + SM_ALO + byte) = lo;
    }
    // ---- bias + Wih0 slice (epilogue CTAs only) ----
    if (role == 0 || role == 1) {
        const float* bi = role ? bih1 : bih0;
        const float* bh = role ? bhh1 : bhh0;
        if (tid < 64) {
            int grow = (tid >> 4) * 512 + m * 16 + (tid & 15);
            ((float*)(sm + SM_BIAS))[tid] = bi[grow] + bh[grow];
        }
        if (role == 0 && tid < 512) {
            int r = tid >> 3, k = tid & 7;
            int grow = (r >> 4) * 512 + m * 16 + (r & 15);
            ((float*)(sm + SM_WI0))[tid] = wih0[grow * 8 + k];
        }
    }
    __syncthreads();

    // lane-derived ldmatrix address pieces
    const unsigned aRow = (unsigned)((l & 15) * 1024);
    const unsigned aX   = (unsigned)(l & 7);
    const unsigned aK   = (unsigned)(l >> 4);
    const unsigned bN   = (unsigned)((wid * 16 + (l & 7)) * 80);
    const unsigned bK16 = (unsigned)(((l >> 3) & 1) * 16);

    float cst[8];
    #pragma unroll
    for (int i = 0; i < 8; ++i) cst[i] = 0.f;

    float acc[4][2][4];

    // =================== tick loop (t = 0..512) ===================
    #pragma unroll 1
    for (int t = 0; t <= T_STEPS; ++t) {
        // -------- phase A: MMA --------
        bool mma_on = (role == 0) ? (t >= 1 && t <= 511)
                    : (role == 1) ? (t >= 1)
                                  : (t >= 2);
        if (mma_on) {
            int par = (role == 2) ? (t & 1) : ((t - 1) & 1);
            int lay = (role == 2) ? 1 : 0;
            const __nv_bfloat16* hiS = &g_hhi[lay][par][0][0];
            const __nv_bfloat16* loS = &g_hlo[lay][par][0][0];

            #pragma unroll
            for (int g = 0; g < 4; ++g)
                #pragma unroll
                for (int nt = 0; nt < 2; ++nt)
                    #pragma unroll
                    for (int i = 0; i < 4; ++i) acc[g][nt][i] = 0.f;

            // stage chunk 0
            {
                #pragma unroll
                for (int q = 0; q < 4; ++q) {
                    int idx = tid + q * NT;
                    int part = idx >> 10, r = idx & 1023, n = r >> 2, cc = r & 3;
                    const __nv_bfloat16* src = (part ? loS : hiS) + n * 512 + 0 * 32 + cc * 8;
                    cpasync16(smb + SM_BBUF(0) + part * 20480 + n * 80 + cc * 16, src);
                }
                asm volatile("cp.async.commit_group;" ::: "memory");
            }

            #pragma unroll 1
            for (int kc = 0; kc < 16; ++kc) {
                if (kc < 15) {
                    #pragma unroll
                    for (int q = 0; q < 4; ++q) {
                        int idx = tid + q * NT;
                        int part = idx >> 10, r = idx & 1023, n = r >> 2, cc = r & 3;
                        const __nv_bfloat16* src = (part ? loS : hiS) + n * 512 + (kc + 1) * 32 + cc * 8;
                        cpasync16(smb + SM_BBUF((kc + 1) & 1) + part * 20480 + n * 80 + cc * 16, src);
                    }
                    asm volatile("cp.async.commit_group;" ::: "memory");
                    asm volatile("cp.async.wait_group 1;" ::: "memory");
                } else {
                    asm volatile("cp.async.wait_group 0;" ::: "memory");
                }
                __syncthreads();

                const unsigned bbase = smb + SM_BBUF(kc & 1);
                #pragma unroll
                for (int ks = 0; ks < 2; ++ks) {
                    unsigned bf[2][2][2];
                    #pragma unroll
                    for (int nt = 0; nt < 2; ++nt)
                        #pragma unroll
                        for (int hl = 0; hl < 2; ++hl)
                            ldm_x2(bf[nt][hl],
                                   bbase + hl * 20480 + bN + nt * 640 + ks * 32 + bK16);
                    #pragma unroll
                    for (int g = 0; g < 4; ++g) {
                        unsigned ch = (((unsigned)(kc * 4 + ks * 2) + aK) ^ aX) << 4;
                        unsigned ahi[4], alo[4];
                        ldm_x4(ahi, smb + SM_AHI + g * 16384 + aRow + ch);
                        ldm_x4(alo, smb + SM_ALO + g * 16384 + aRow + ch);
                        #pragma unroll
                        for (int nt = 0; nt < 2; ++nt) {
                            mma16816(acc[g][nt], ahi, bf[nt][0]);   // Whi*hhi
                            mma16816(acc[g][nt], ahi, bf[nt][1]);   // Whi*hlo
                            mma16816(acc[g][nt], alo, bf[nt][0]);   // Wlo*hhi
                        }
                    }
                }
                __syncthreads();
            }

            if (role == 2) {   // store partials for L1
                #pragma unroll
                for (int g = 0; g < 4; ++g)
                    #pragma unroll
                    for (int nt = 0; nt < 2; ++nt) {
                        int r0 = g * 16 + (l >> 2);
                        int c  = wid * 16 + nt * 8 + 2 * (l & 3);
                        *(float2*)&g_Dp[m][r0][c]     = make_float2(acc[g][nt][0], acc[g][nt][1]);
                        *(float2*)&g_Dp[m][r0 + 8][c] = make_float2(acc[g][nt][2], acc[g][nt][3]);
                    }
            }
        }
        grid_barrier();

        // -------- phase B: epilogue --------
        bool epi_on = (role == 0) ? (t <= 511) : (role == 1);
        if (role == 1 && t == 0) epi_on = false;
        if (epi_on) {
            const int step = (role == 0) ? t : t - 1;
            const float* BIAS = (const float*)(sm + SM_BIAS);
            const float* WI0  = (const float*)(sm + SM_WI0);
            unsigned* hstg = (unsigned*)(sm + SM_HSTG);
            const bool useacc = mma_on;

            #pragma unroll
            for (int nt = 0; nt < 2; ++nt) {
                int cb = wid * 16 + nt * 8 + 2 * (l & 3);
                float uv[2][8];
                if (role == 0) {
                    #pragma unroll
                    for (int d = 0; d < 2; ++d) {
                        const float4* up = (const float4*)(u + ((size_t)(cb + d) * T_STEPS + step) * 8);
                        float4 a = __ldg(up), bq = __ldg(up + 1);
                        uv[d][0] = a.x; uv[d][1] = a.y; uv[d][2] = a.z; uv[d][3] = a.w;
                        uv[d][4] = bq.x; uv[d][5] = bq.y; uv[d][6] = bq.z; uv[d][7] = bq.w;
                    }
                }
                #pragma unroll
                for (int half = 0; half < 2; ++half) {
                    int uu = (l >> 2) + half * 8;
                    float pre[4][2];
                    #pragma unroll
                    for (int g = 0; g < 4; ++g) {
                        float b0 = BIAS[g * 16 + uu];
                        pre[g][0] = b0 + (useacc ? acc[g][nt][half * 2 + 0] : 0.f);
                        pre[g][1] = b0 + (useacc ? acc[g][nt][half * 2 + 1] : 0.f);
                        if (role == 1 && t >= 2) {
                            float2 dp = __ldcg((const float2*)&g_Dp[m][g * 16 + uu][cb]);
                            pre[g][0] += dp.x; pre[g][1] += dp.y;
                        }
                        if (role == 0) {
                            const float* wr = WI0 + (g * 16 + uu) * 8;
                            #pragma unroll
                            for (int d = 0; d < 2; ++d) {
                                float s = 0.f;
                                #pragma unroll
                                for (int k = 0; k < 8; ++k) s += wr[k] * uv[d][k];
                                pre[g][d] += s;
                            }
                        }
                    }
                    #pragma unroll
                    for (int d = 0; d < 2; ++d) {
                        int s = nt * 4 + half * 2 + d;
                        float ig = sigx(pre[0][d]), fg = sigx(pre[1][d]);
                        float gg = tanhf(pre[2][d]), og = sigx(pre[3][d]);
                        float c = fg * cst[s] + ig * gg;
                        cst[s] = c;
                        float h = og * tanhf(c);
                        __nv_bfloat16 hh = __float2bfloat16(h);
                        __nv_bfloat16 hl2 = __float2bfloat16(h - __bfloat162float(hh));
                        __nv_bfloat162 pk; pk.x = hh; pk.y = hl2;
                        hstg[uu * 256 + cb + d] = *(unsigned*)&pk;
                    }
                }
            }
            __syncthreads();
            // coalesced writeback: thread -> (part, b), 16 units
            {
                int part = tid & 1, b = tid >> 1;
                int lay = (role == 0) ? 0 : 1;
                int par = (role == 0) ? (t & 1) : ((t - 1) & 1);
                unsigned o[8];
                #pragma unroll
                for (int i = 0; i < 8; ++i) {
                    unsigned p0 = hstg[(2 * i) * 256 + b];
                    unsigned p1 = hstg[(2 * i + 1) * 256 + b];
                    unsigned v0 = part ? (p0 >> 16) : (p0 & 0xFFFFu);
                    unsigned v1 = part ? (p1 >> 16) : (p1 & 0xFFFFu);
                    o[i] = v0 | (v1 << 16);
                }
                __nv_bfloat16* dst = (part ? &g_hlo[lay][par][0][0] : &g_hhi[lay][par][0][0])
                                     + (size_t)b * 512 + m * 16;
                ((uint4*)dst)[0] = make_uint4(o[0], o[1], o[2], o[3]);
                ((uint4*)dst)[1] = make_uint4(o[4], o[5], o[6], o[7]);
            }
        }
        grid_barrier();
    }

    // =================== FC head stage A ===================
    for (int cell = cta * NT + tid; cell < 256 * 256; cell += NCTA * NT) {
        int r = cell & 255, b = cell >> 8;
        const float* wrow = fcw0 + (size_t)r * 512;
        const __nv_bfloat16* Hh = &g_hhi[1][1][b][0];
        const __nv_bfloat16* Hl = &g_hlo[1][1][b][0];
        float accf = 0.f;
        for (int k = 0; k < 512; k += 8) {
            uint4 vh = __ldcg((const uint4*)(Hh + k));
            uint4 vl = __ldcg((const uint4*)(Hl + k));
            const __nv_bfloat162* ph = (const __nv_bfloat162*)&vh;
            const __nv_bfloat162* pl = (const __nv_bfloat162*)&vl;
            #pragma unroll
            for (int i = 0; i < 4; ++i) {
                float2 a2 = __bfloat1622float2(ph[i]);
                float2 b2 = __bfloat1622float2(pl[i]);
                accf += wrow[k + 2 * i] * (a2.x + b2.x) + wrow[k + 2 * i + 1] * (a2.y + b2.y);
            }
        }
        g_fch[r][b] = tanhf(accf + __ldg(fcb0 + r));
    }
    grid_barrier();

    // =================== FC head stage B ===================
    if (cta == 0 && tid < 256) {
        int b = tid;
        float s0 = __ldg(fcb1 + 0), s1 = __ldg(fcb1 + 1);
        #pragma unroll 8
        for (int k = 0; k < 256; ++k) {
            float v = __ldcg(&g_fch[k][b]);
            s0 += v * __ldg(fcw1 + k);
            s1 += v * __ldg(fcw1 + 256 + k);
        }
        const float scale = 0.5f * (4.2f - 2.5f);
        out[b * 2 + 0] = (s0 + 1.0f) * scale + 2.5f;
        out[b * 2 + 1] = (s1 + 1.0f) * scale + 2.5f;
    }
}

// ---------------------------------------------------------------------------
extern "C" void kernel_launch(void* const* d_in, const int* in_sizes, int n_in,
                              void* d_out, int out_size) {
    (void)in_sizes; (void)n_in; (void)out_size;
    const float* u    = (const float*)d_in[0];
    const float* wih0 = (const float*)d_in[1];
    const float* whh0 = (const float*)d_in[2];
    const float* bih0 = (const float*)d_in[3];
    const float* bhh0 = (const float*)d_in[4];
    const float* wih1 = (const float*)d_in[5];
    const float* whh1 = (const float*)d_in[6];
    const float* bih1 = (const float*)d_in[7];
    const float* bhh1 = (const float*)d_in[8];
    const float* fcw0 = (const float*)d_in[9];
    const float* fcb0 = (const float*)d_in[10];
    const float* fcw1 = (const float*)d_in[11];
    const float* fcb1 = (const float*)d_in[12];
    float* out = (float*)d_out;

    cudaFuncSetAttribute(lstm_hmma,
                         cudaFuncAttributeMaxDynamicSharedMemorySize, SMEM_ALLOC);
    lstm_hmma<<<NCTA, NT, SMEM_ALLOC>>>(
        u, wih0, whh0, bih0, bhh0, wih1, whh1, bih1, bhh1,
        fcw0, fcb0, fcw1, fcb1, out);
}

// round 11
// speedup vs baseline: 2.0045x; 1.0407x over previous
#include <cuda_runtime.h>
#include <cuda_bf16.h>

#define T_STEPS 512
#define NCTA    96
#define NT      512

// ---------------- SMEM byte offsets (from 128B-aligned base) ---------------
#define SM_AHI   0                         // 64x512 bf16, swizzled (64KB)
#define SM_ALO   65536                     // 64KB
#define SM_BBUF(bs) (131072 + (bs)*40960)  // 2 bufs x (hi 20480 + lo 20480)
#define SM_HSTG  131072                    // reused in epilogue: 16 x 256 u32
#define SM_BIAS  212992                    // 64 f32
#define SM_WI0   213248                    // 64x8 f32
#define SMEM_ALLOC (215296 + 256)

// ---------------- global scratch -------------------------------------------
__device__ __nv_bfloat16 g_hhi[2][2][256][512];   // [layer][parity][b][k]
__device__ __nv_bfloat16 g_hlo[2][2][256][512];
__device__ float g_Dp[2][32][64][256];            // Wih1 partials, double buffered
__device__ float g_fch[256][256];                 // [row][b]
__device__ unsigned g_arrive = 0;
__device__ unsigned g_gen    = 0;

__device__ __forceinline__ float sigx(float x)  { return 1.0f / (1.0f + __expf(-x)); }
__device__ __forceinline__ float tanhx(float x) { return 2.0f / (1.0f + __expf(-2.0f * x)) - 1.0f; }

__device__ __forceinline__ unsigned smem_u32(const void* p) {
    unsigned a;
    asm("{ .reg .u64 t; cvta.to.shared.u64 t, %1; cvt.u32.u64 %0, t; }" : "=r"(a) : "l"(p));
    return a;
}
__device__ __forceinline__ void ldm_x4(unsigned* r, unsigned addr) {
    asm volatile("ldmatrix.sync.aligned.m8n8.x4.shared.b16 {%0,%1,%2,%3}, [%4];"
        : "=r"(r[0]), "=r"(r[1]), "=r"(r[2]), "=r"(r[3]) : "r"(addr));
}
// B tile is n-major (row = batch column, k contiguous) => NON-trans ldmatrix.
__device__ __forceinline__ void ldm_x2(unsigned* r, unsigned addr) {
    asm volatile("ldmatrix.sync.aligned.m8n8.x2.shared.b16 {%0,%1}, [%2];"
        : "=r"(r[0]), "=r"(r[1]) : "r"(addr));
}
__device__ __forceinline__ void mma16816(float* c, const unsigned* a, const unsigned* b) {
    asm volatile(
        "mma.sync.aligned.m16n8k16.row.col.f32.bf16.bf16.f32 "
        "{%0,%1,%2,%3}, {%4,%5,%6,%7}, {%8,%9}, {%0,%1,%2,%3};"
        : "+f"(c[0]), "+f"(c[1]), "+f"(c[2]), "+f"(c[3])
        : "r"(a[0]), "r"(a[1]), "r"(a[2]), "r"(a[3]), "r"(b[0]), "r"(b[1]));
}
__device__ __forceinline__ void cpasync16(unsigned dst, const void* src) {
    asm volatile("cp.async.cg.shared.global [%0], [%1], 16;" :: "r"(dst), "l"(src));
}

// ---------------- grid barrier (generation counter) ------------------------
__device__ __forceinline__ void grid_barrier() {
    __syncthreads();
    if (threadIdx.x == 0) {
        __threadfence();
        volatile unsigned* genp = &g_gen;
        unsigned snap = *genp;
        unsigned old = atomicAdd(&g_arrive, 1u);
        if (old == (unsigned)(NCTA - 1)) {
            g_arrive = 0u;
            __threadfence();
            atomicAdd(&g_gen, 1u);
        } else {
            while (*genp == snap) { }
        }
        __threadfence();
    }
    __syncthreads();
}

// ---------------------------------------------------------------------------
// Fused 1-barrier-per-tick schedule:
//  role0 (cta 0..31):  tick t: MMA Whh0*h0[t-1] + fused epilogue -> h0[t]      (t=0..511)
//  role1 (cta 32..63): tick t: MMA Wih1*h0[t-1] -> g_Dp[(t-1)&1]               (t=1..512)
//  role2 (cta 64..95): tick t: MMA Whh1*h1[t-3] + epilogue(+g_Dp[t&1]) -> h1[t-2] (epi t=2..513)
__global__ void __launch_bounds__(NT, 1)
lstm_hmma(const float* __restrict__ u,
          const float* __restrict__ wih0, const float* __restrict__ whh0,
          const float* __restrict__ bih0, const float* __restrict__ bhh0,
          const float* __restrict__ wih1, const float* __restrict__ whh1,
          const float* __restrict__ bih1, const float* __restrict__ bhh1,
          const float* __restrict__ fcw0, const float* __restrict__ fcb0,
          const float* __restrict__ fcw1, const float* __restrict__ fcb1,
          float* __restrict__ out)
{
    extern __shared__ char smraw[];
    char* sm = (char*)((((unsigned long long)(size_t)smraw) + 127) & ~127ULL);
    const unsigned smb = smem_u32(sm);
    const int tid = threadIdx.x, wid = tid >> 5, l = tid & 31;
    const int cta = blockIdx.x;

    const int role = cta >> 5;
    const int m    = cta & 31;          // row-slice: units j0 = m*16
    const float* Asrc = (role == 0) ? whh0 : (role == 1) ? wih1 : whh1;

    // ---- one-time A staging: bf16 hi/lo, row r = g*16+jj, XOR-16B-chunk swizzle
    for (int idx = tid; idx < 64 * 512; idx += NT) {
        int r = idx >> 9, k = idx & 511;
        int grow = (r >> 4) * 512 + m * 16 + (r & 15);
        float w = Asrc[(size_t)grow * 512 + k];
        __nv_bfloat16 hi = __float2bfloat16(w);
        __nv_bfloat16 lo = __float2bfloat16(w - __bfloat162float(hi));
        int chunk = (k >> 3) ^ (r & 7);
        int byte  = r * 1024 + (chunk << 4) + (k & 7) * 2;
        *(__nv_bfloat16*)(sm + SM_AHI + byte) = hi;
        *(__nv_bfloat16*)(sm + SM_ALO + byte) = lo;
    }
    // ---- bias + Wih0 slice (epilogue CTAs: role 0 and 2) ----
    if (role == 0 || role == 2) {
        const float* bi = (role == 2) ? bih1 : bih0;
        const float* bh = (role == 2) ? bhh1 : bhh0;
        if (tid < 64) {
            int grow = (tid >> 4) * 512 + m * 16 + (tid & 15);
            ((float*)(sm + SM_BIAS))[tid] = bi[grow] + bh[grow];
        }
        if (role == 0 && tid < 512) {
            int r = tid >> 3, k = tid & 7;
            int grow = (r >> 4) * 512 + m * 16 + (r & 15);
            ((float*)(sm + SM_WI0))[tid] = wih0[grow * 8 + k];
        }
    }
    __syncthreads();

    // lane-derived ldmatrix address pieces
    const unsigned aRow = (unsigned)((l & 15) * 1024);
    const unsigned aX   = (unsigned)(l & 7);
    const unsigned aK   = (unsigned)(l >> 4);
    const unsigned bN   = (unsigned)((wid * 16 + (l & 7)) * 80);
    const unsigned bK16 = (unsigned)(((l >> 3) & 1) * 16);

    float cst[8];
    #pragma unroll
    for (int i = 0; i < 8; ++i) cst[i] = 0.f;

    float acc[4][2][4];

    // =================== tick loop (t = 0..513), ONE barrier per tick ======
    #pragma unroll 1
    for (int t = 0; t <= T_STEPS + 1; ++t) {
        bool mma_on = (role == 0) ? (t >= 1 && t <= 511)
                    : (role == 1) ? (t >= 1 && t <= 512)
                                  : (t >= 3);
        if (mma_on) {
            // all roles read parity (t-1)&1; role2 reads layer 1 (h1[t-3])
            int par = (t - 1) & 1;
            int lay = (role == 2) ? 1 : 0;
            const __nv_bfloat16* hiS = &g_hhi[lay][par][0][0];
            const __nv_bfloat16* loS = &g_hlo[lay][par][0][0];

            #pragma unroll
            for (int g = 0; g < 4; ++g)
                #pragma unroll
                for (int nt = 0; nt < 2; ++nt)
                    #pragma unroll
                    for (int i = 0; i < 4; ++i) acc[g][nt][i] = 0.f;

            // prologue: stage chunk 0
            #pragma unroll
            for (int q = 0; q < 4; ++q) {
                int idx = tid + q * NT;
                int part = idx >> 10, r = idx & 1023, n = r >> 2, cc = r & 3;
                const __nv_bfloat16* src = (part ? loS : hiS) + n * 512 + cc * 8;
                cpasync16(smb + SM_BBUF(0) + part * 20480 + n * 80 + cc * 16, src);
            }
            asm volatile("cp.async.commit_group;" ::: "memory");

            #pragma unroll 1
            for (int kc = 0; kc < 16; ++kc) {
                asm volatile("cp.async.wait_group 0;" ::: "memory");
                __syncthreads();                       // buf kc visible; prev MMAs issued
                if (kc < 15) {                          // issue next into other buffer
                    #pragma unroll
                    for (int q = 0; q < 4; ++q) {
                        int idx = tid + q * NT;
                        int part = idx >> 10, r = idx & 1023, n = r >> 2, cc = r & 3;
                        const __nv_bfloat16* src = (part ? loS : hiS) + n * 512 + (kc + 1) * 32 + cc * 8;
                        cpasync16(smb + SM_BBUF((kc + 1) & 1) + part * 20480 + n * 80 + cc * 16, src);
                    }
                    asm volatile("cp.async.commit_group;" ::: "memory");
                }
                const unsigned bbase = smb + SM_BBUF(kc & 1);
                #pragma unroll
                for (int ks = 0; ks < 2; ++ks) {
                    unsigned bf[2][2][2];
                    #pragma unroll
                    for (int nt = 0; nt < 2; ++nt)
                        #pragma unroll
                        for (int hl = 0; hl < 2; ++hl)
                            ldm_x2(bf[nt][hl],
                                   bbase + hl * 20480 + bN + nt * 640 + ks * 32 + bK16);
                    #pragma unroll
                    for (int g = 0; g < 4; ++g) {
                        unsigned ch = (((unsigned)(kc * 4 + ks * 2) + aK) ^ aX) << 4;
                        unsigned ahi[4], alo[4];
                        ldm_x4(ahi, smb + SM_AHI + g * 16384 + aRow + ch);
                        ldm_x4(alo, smb + SM_ALO + g * 16384 + aRow + ch);
                        #pragma unroll
                        for (int nt = 0; nt < 2; ++nt) {
                            mma16816(acc[g][nt], ahi, bf[nt][0]);   // Whi*hhi
                            mma16816(acc[g][nt], ahi, bf[nt][1]);   // Whi*hlo
                            mma16816(acc[g][nt], alo, bf[nt][0]);   // Wlo*hhi
                        }
                    }
                }
            }
            __syncthreads();   // all MMA reads done before buf area reuse (hstg)

            if (role == 1) {   // store Wih1 partials for role2's next tick
                float* Dp = &g_Dp[(t - 1) & 1][m][0][0];
                #pragma unroll
                for (int g = 0; g < 4; ++g)
                    #pragma unroll
                    for (int nt = 0; nt < 2; ++nt) {
                        int r0 = g * 16 + (l >> 2);
                        int c  = wid * 16 + nt * 8 + 2 * (l & 3);
                        float2 v0 = make_float2(acc[g][nt][0], acc[g][nt][1]);
                        float2 v1 = make_float2(acc[g][nt][2], acc[g][nt][3]);
                        __stcg((float2*)(Dp + (size_t)r0 * 256 + c), v0);
                        __stcg((float2*)(Dp + (size_t)(r0 + 8) * 256 + c), v1);
                    }
            }
        }

        // -------- fused epilogue (roles 0 and 2) --------
        bool epi_on = (role == 0) ? (t <= 511) : (role == 2) ? (t >= 2) : false;
        if (epi_on) {
            const int step = (role == 0) ? t : t - 2;     // LSTM step index
            const float* BIAS = (const float*)(sm + SM_BIAS);
            const float* WI0  = (const float*)(sm + SM_WI0);
            unsigned* hstg = (unsigned*)(sm + SM_HSTG);
            const bool useacc = mma_on;
            const float* Dp = (role == 2) ? &g_Dp[t & 1][m][0][0] : 0;

            #pragma unroll
            for (int nt = 0; nt < 2; ++nt) {
                int cb = wid * 16 + nt * 8 + 2 * (l & 3);
                float uv[2][8];
                if (role == 0) {
                    #pragma unroll
                    for (int d = 0; d < 2; ++d) {
                        const float4* up = (const float4*)(u + ((size_t)(cb + d) * T_STEPS + step) * 8);
                        float4 a = __ldg(up), bq = __ldg(up + 1);
                        uv[d][0] = a.x; uv[d][1] = a.y; uv[d][2] = a.z; uv[d][3] = a.w;
                        uv[d][4] = bq.x; uv[d][5] = bq.y; uv[d][6] = bq.z; uv[d][7] = bq.w;
                    }
                }
                #pragma unroll
                for (int half = 0; half < 2; ++half) {
                    int uu = (l >> 2) + half * 8;
                    float pre[4][2];
                    #pragma unroll
                    for (int g = 0; g < 4; ++g) {
                        float b0 = BIAS[g * 16 + uu];
                        pre[g][0] = b0 + (useacc ? acc[g][nt][half * 2 + 0] : 0.f);
                        pre[g][1] = b0 + (useacc ? acc[g][nt][half * 2 + 1] : 0.f);
                        if (role == 2) {
                            float2 dp = __ldcg((const float2*)(Dp + (size_t)(g * 16 + uu) * 256 + cb));
                            pre[g][0] += dp.x; pre[g][1] += dp.y;
                        }
                        if (role == 0) {
                            const float* wr = WI0 + (g * 16 + uu) * 8;
                            #pragma unroll
                            for (int d = 0; d < 2; ++d) {
                                float s = 0.f;
                                #pragma unroll
                                for (int k = 0; k < 8; ++k) s += wr[k] * uv[d][k];
                                pre[g][d] += s;
                            }
                        }
                    }
                    #pragma unroll
                    for (int d = 0; d < 2; ++d) {
                        int s = nt * 4 + half * 2 + d;
                        float ig = sigx(pre[0][d]), fg = sigx(pre[1][d]);
                        float gg = tanhx(pre[2][d]), og = sigx(pre[3][d]);
                        float c = fg * cst[s] + ig * gg;
                        cst[s] = c;
                        float h = og * tanhx(c);
                        __nv_bfloat16 hh = __float2bfloat16(h);
                        __nv_bfloat16 hl2 = __float2bfloat16(h - __bfloat162float(hh));
                        __nv_bfloat162 pk; pk.x = hh; pk.y = hl2;
                        hstg[uu * 256 + cb + d] = *(unsigned*)&pk;
                    }
                }
            }
            __syncthreads();
            // coalesced writeback: thread -> (part, b), 16 units
            {
                int part = tid & 1, b = tid >> 1;
                int lay = (role == 0) ? 0 : 1;
                int par = step & 1;
                unsigned o[8];
                #pragma unroll
                for (int i = 0; i < 8; ++i) {
                    unsigned p0 = hstg[(2 * i) * 256 + b];
                    unsigned p1 = hstg[(2 * i + 1) * 256 + b];
                    unsigned v0 = part ? (p0 >> 16) : (p0 & 0xFFFFu);
                    unsigned v1 = part ? (p1 >> 16) : (p1 & 0xFFFFu);
                    o[i] = v0 | (v1 << 16);
                }
                __nv_bfloat16* dst = (part ? &g_hlo[lay][par][0][0] : &g_hhi[lay][par][0][0])
                                     + (size_t)b * 512 + m * 16;
                ((uint4*)dst)[0] = make_uint4(o[0], o[1], o[2], o[3]);
                ((uint4*)dst)[1] = make_uint4(o[4], o[5], o[6], o[7]);
            }
        }
        grid_barrier();
    }

    // =================== FC head stage A ===================
    for (int cell = cta * NT + tid; cell < 256 * 256; cell += NCTA * NT) {
        int r = cell & 255, b = cell >> 8;
        const float* wrow = fcw0 + (size_t)r * 512;
        const __nv_bfloat16* Hh = &g_hhi[1][1][b][0];   // h1[511], parity 1
        const __nv_bfloat16* Hl = &g_hlo[1][1][b][0];
        float accf = 0.f;
        for (int k = 0; k < 512; k += 8) {
            uint4 vh = __ldcg((const uint4*)(Hh + k));
            uint4 vl = __ldcg((const uint4*)(Hl + k));
            const __nv_bfloat162* ph = (const __nv_bfloat162*)&vh;
            const __nv_bfloat162* pl = (const __nv_bfloat162*)&vl;
            #pragma unroll
            for (int i = 0; i < 4; ++i) {
                float2 a2 = __bfloat1622float2(ph[i]);
                float2 b2 = __bfloat1622float2(pl[i]);
                accf += wrow[k + 2 * i] * (a2.x + b2.x) + wrow[k + 2 * i + 1] * (a2.y + b2.y);
            }
        }
        g_fch[r][b] = tanhf(accf + __ldg(fcb0 + r));
    }
    grid_barrier();

    // =================== FC head stage B ===================
    if (cta == 0 && tid < 256) {
        int b = tid;
        float s0 = __ldg(fcb1 + 0), s1 = __ldg(fcb1 + 1);
        #pragma unroll 8
        for (int k = 0; k < 256; ++k) {
            float v = __ldcg(&g_fch[k][b]);
            s0 += v * __ldg(fcw1 + k);
            s1 += v * __ldg(fcw1 + 256 + k);
        }
        const float scale = 0.5f * (4.2f - 2.5f);
        out[b * 2 + 0] = (s0 + 1.0f) * scale + 2.5f;
        out[b * 2 + 1] = (s1 + 1.0f) * scale + 2.5f;
    }
}

// ---------------------------------------------------------------------------
extern "C" void kernel_launch(void* const* d_in, const int* in_sizes, int n_in,
                              void* d_out, int out_size) {
    (void)in_sizes; (void)n_in; (void)out_size;
    const float* u    = (const float*)d_in[0];
    const float* wih0 = (const float*)d_in[1];
    const float* whh0 = (const float*)d_in[2];
    const float* bih0 = (const float*)d_in[3];
    const float* bhh0 = (const float*)d_in[4];
    const float* wih1 = (const float*)d_in[5];
    const float* whh1 = (const float*)d_in[6];
    const float* bih1 = (const float*)d_in[7];
    const float* bhh1 = (const float*)d_in[8];
    const float* fcw0 = (const float*)d_in[9];
    const float* fcb0 = (const float*)d_in[10];
    const float* fcw1 = (const float*)d_in[11];
    const float* fcb1 = (const float*)d_in[12];
    float* out = (float*)d_out;

    cudaFuncSetAttribute(lstm_hmma,
                         cudaFuncAttributeMaxDynamicSharedMemorySize, SMEM_ALLOC);
    lstm_hmma<<<NCTA, NT, SMEM_ALLOC>>>(
        u, wih0, whh0, bih0, bhh0, wih1, whh1, bih1, bhh1,
        fcw0, fcb0, fcw1, fcb1, out);
}